// round 5
// baseline (speedup 1.0000x reference)
#include <cuda_runtime.h>
#include <cuda_fp16.h>
#include <cstdint>

// ============================================================================
// QuantLinear: out[M,N] = x[M,K] @ dequant(qweight, scales, qzeros)[K,N]
// M=8192, K=4096, N=11008, groupsize=128, 4-bit.
//
// compute_103 PTX target => no tcgen05; tensor path = mma.sync HMMA (rt=8
// measured). Floor for this GEMM = 1.22ms; design goal = tensor% >= 88.
//
// Pass 1: fused prep: x fp32 -> g_X fp16 [M,K]; dequant -> g_W fp16 [N,K].
// Pass 2: GEMM, CUTLASS-sm80 shape: CTA 128x256x64, 256 thr, 8 warps of
//         64x64, 4-stage cp.async pipeline, ks-level fragment double-buffer.
// ============================================================================

constexpr int M = 8192;
constexpr int N = 11008;
constexpr int K = 4096;

constexpr int BM = 128;
constexpr int BN = 256;
constexpr int KC = 64;             // halves per stage = 128B rows (SW128)
constexpr int STAGES = 4;
constexpr int NK = K / KC;         // 64
constexpr int THREADS = 256;

constexpr int A_BYTES = BM * 128;                   // 16384
constexpr int B_BYTES = BN * 128;                   // 32768
constexpr int STAGE_BYTES = A_BYTES + B_BYTES;      // 49152
constexpr int SMEM_BYTES = STAGES * STAGE_BYTES;    // 196608 (<= 227KB)

constexpr int XWORK = M * K / 4;        // float4 items in convert part
constexpr int WWORK = (K / 8) * N;      // int32 items in dequant part

static_assert(M % BM == 0 && N % BN == 0 && K % KC == 0, "exact tiling");

__device__ __half g_X[(size_t)M * K];   // [M, K] fp16
__device__ __half g_W[(size_t)N * K];   // [N, K] fp16 (W^T), K-major

// ----------------------------------------------------------------------------
// helpers
// ----------------------------------------------------------------------------
__device__ __forceinline__ void cp16(uint32_t smem_dst, const void* gsrc) {
    asm volatile("cp.async.cg.shared.global [%0], [%1], 16;"
                 :: "r"(smem_dst), "l"(gsrc));
}

__device__ __forceinline__ void ldsm4(uint32_t* r, uint32_t addr) {
    asm volatile("ldmatrix.sync.aligned.m8n8.x4.shared.b16 {%0,%1,%2,%3}, [%4];"
                 : "=r"(r[0]), "=r"(r[1]), "=r"(r[2]), "=r"(r[3]) : "r"(addr));
}

__device__ __forceinline__ void mma16816(float* c, const uint32_t* a, const uint32_t* b) {
    asm volatile(
        "mma.sync.aligned.m16n8k16.row.col.f32.f16.f16.f32 "
        "{%0,%1,%2,%3}, {%4,%5,%6,%7}, {%8,%9}, {%0,%1,%2,%3};"
        : "+f"(c[0]), "+f"(c[1]), "+f"(c[2]), "+f"(c[3])
        : "r"(a[0]), "r"(a[1]), "r"(a[2]), "r"(a[3]), "r"(b[0]), "r"(b[1]));
}

// ----------------------------------------------------------------------------
// Pass 1: fused x-convert + dequant
// ----------------------------------------------------------------------------
__global__ void __launch_bounds__(256)
prep_kernel(const float* __restrict__ x, const int* __restrict__ qweight,
            const float* __restrict__ scales, const int* __restrict__ qzeros) {
    int idx = blockIdx.x * 256 + threadIdx.x;
    if (idx < XWORK) {
        float4 v = ((const float4*)x)[idx];
        __half2 h0 = __floats2half2_rn(v.x, v.y);
        __half2 h1 = __floats2half2_rn(v.z, v.w);
        uint2 o;
        o.x = *(unsigned*)&h0;
        o.y = *(unsigned*)&h1;
        ((uint2*)g_X)[idx] = o;
        return;
    }
    int widx = idx - XWORK;          // over (K/8)*N
    if (widx >= WWORK) return;
    int n = widx % N;
    int r = widx / N;
    int g = r >> 4;                  // groupsize 128 = 16 qweight rows
    unsigned q  = ((const unsigned*)qweight)[widx];
    unsigned qz = ((const unsigned*)qzeros)[g * (N / 8) + (n >> 3)];
    float z = (float)((qz >> ((n & 7) * 4)) & 0xF);
    float s = scales[g * N + n];
    __half2 outv[4];
#pragma unroll
    for (int j = 0; j < 4; j++) {
        float v0 = s * ((float)((q >> (8 * j))     & 0xF) - z);
        float v1 = s * ((float)((q >> (8 * j + 4)) & 0xF) - z);
        outv[j] = __floats2half2_rn(v0, v1);
    }
    *(uint4*)&g_W[(size_t)n * K + r * 8] = *(uint4*)outv;
}

// ----------------------------------------------------------------------------
// Stage loader (256 threads): A 128 rows + B 256 rows, 128B/row, SW128.
// Row r, 16B chunk c at r*128 + ((c ^ (r&7))*16).
// ----------------------------------------------------------------------------
__device__ __forceinline__ void load_stage(uint32_t sbase, int slot, int kt,
                                           const __half* Ag, const __half* Bg,
                                           int tid) {
    const uint32_t a_s = sbase + slot * STAGE_BYTES;
    const uint32_t b_s = a_s + A_BYTES;
    const __half* Ak = Ag + kt * KC;
    const __half* Bk = Bg + kt * KC;
#pragma unroll
    for (int it = 0; it < 4; it++) {        // 128*8 / 256
        int idx = tid + it * THREADS;
        int r = idx >> 3, c = idx & 7;
        uint32_t off = (uint32_t)r * 128 + (uint32_t)((c ^ (r & 7)) * 16);
        cp16(a_s + off, Ak + (size_t)r * K + c * 8);
    }
#pragma unroll
    for (int it = 0; it < 8; it++) {        // 256*8 / 256
        int idx = tid + it * THREADS;
        int r = idx >> 3, c = idx & 7;
        uint32_t off = (uint32_t)r * 128 + (uint32_t)((c ^ (r & 7)) * 16);
        cp16(b_s + off, Bk + (size_t)r * K + c * 8);
    }
}

// ----------------------------------------------------------------------------
// Pass 2: GEMM
// ----------------------------------------------------------------------------
__global__ void __launch_bounds__(THREADS)
gemm_kernel(float* __restrict__ out) {
    extern __shared__ char smem[];
    const uint32_t sbase = (uint32_t)__cvta_generic_to_shared(smem);
    const int tid  = threadIdx.x;
    const int warp = tid >> 5;
    const int lane = tid & 31;
    const int wm = warp & 1;          // 2 warps over 128 M (64 each)
    const int wn = warp >> 1;         // 4 warps over 256 N (64 each)
    const int m0 = blockIdx.x * BM;
    const int n0 = blockIdx.y * BN;

    const __half* Ag = g_X + (size_t)m0 * K;
    const __half* Bg = g_W + (size_t)n0 * K;

    float acc[4][8][4];
#pragma unroll
    for (int i = 0; i < 4; i++)
#pragma unroll
        for (int j = 0; j < 8; j++)
#pragma unroll
            for (int e = 0; e < 4; e++) acc[i][j][e] = 0.f;

    // ldmatrix address components (canonical x4 ordering, validated R2-R4):
    const int arow = wm * 64 + (lane & 15);
    const int asel = lane >> 4;                              // k-chunk +0/+1
    const int brow = wn * 64 + (((lane >> 4) & 1) << 3) + (lane & 7);
    const int bsel = (lane >> 3) & 1;

    // double-buffered fragments
    uint32_t afr[2][4][4], bfr[2][4][4];

    // prologue: fill stages 0..2
#pragma unroll
    for (int s = 0; s < STAGES - 1; s++) {
        load_stage(sbase, s, s, Ag, Bg, tid);
        asm volatile("cp.async.commit_group;" ::: "memory");
    }

    for (int i = 0; i < NK; i++) {
        const int slot = i & (STAGES - 1);
        asm volatile("cp.async.wait_group %0;" :: "n"(STAGES - 2) : "memory");
        __syncthreads();     // stage i resident; stage (i+3)%4 reads finished

        const uint32_t a_s = sbase + slot * STAGE_BYTES;
        const uint32_t b_s = a_s + A_BYTES;

        // load ks=0 fragments into buffer 0
        {
            const int kc = asel;                 // ks*2 + asel, ks=0
#pragma unroll
            for (int mf = 0; mf < 4; mf++) {
                int row = arow + mf * 16;
                ldsm4(afr[0][mf], a_s + row * 128 + ((kc ^ (row & 7)) * 16));
            }
            const int kb = bsel;
#pragma unroll
            for (int nf2 = 0; nf2 < 4; nf2++) {
                int row = brow + nf2 * 16;
                ldsm4(bfr[0][nf2], b_s + row * 128 + ((kb ^ (row & 7)) * 16));
            }
        }

        // issue fill for stage i+3 (overlaps with this stage's MMAs)
        if (i + STAGES - 1 < NK)
            load_stage(sbase, (i + STAGES - 1) & (STAGES - 1), i + STAGES - 1,
                       Ag, Bg, tid);
        asm volatile("cp.async.commit_group;" ::: "memory");

#pragma unroll
        for (int ks = 0; ks < KC / 16; ks++) {
            const int cur = ks & 1;
            if (ks < KC / 16 - 1) {      // prefetch ks+1 fragments
                const int nxt = cur ^ 1;
                const int kc = (ks + 1) * 2 + asel;
#pragma unroll
                for (int mf = 0; mf < 4; mf++) {
                    int row = arow + mf * 16;
                    ldsm4(afr[nxt][mf], a_s + row * 128 + ((kc ^ (row & 7)) * 16));
                }
                const int kb = (ks + 1) * 2 + bsel;
#pragma unroll
                for (int nf2 = 0; nf2 < 4; nf2++) {
                    int row = brow + nf2 * 16;
                    ldsm4(bfr[nxt][nf2], b_s + row * 128 + ((kb ^ (row & 7)) * 16));
                }
            }
#pragma unroll
            for (int mf = 0; mf < 4; mf++)
#pragma unroll
                for (int nf = 0; nf < 8; nf++)
                    mma16816(acc[mf][nf], afr[cur][mf], &bfr[cur][nf >> 1][(nf & 1) * 2]);
        }
    }

    // Epilogue: register -> gmem float2 stores
    const int mbase = m0 + wm * 64 + (lane >> 2);
    const int nbase = n0 + wn * 64 + (lane & 3) * 2;
#pragma unroll
    for (int mf = 0; mf < 4; mf++)
#pragma unroll
        for (int nf = 0; nf < 8; nf++) {
            float* p0 = &out[(size_t)(mbase + mf * 16)     * N + nbase + nf * 8];
            float* p1 = &out[(size_t)(mbase + mf * 16 + 8) * N + nbase + nf * 8];
            *(float2*)p0 = make_float2(acc[mf][nf][0], acc[mf][nf][1]);
            *(float2*)p1 = make_float2(acc[mf][nf][2], acc[mf][nf][3]);
        }
}

// ----------------------------------------------------------------------------
extern "C" void kernel_launch(void* const* d_in, const int* in_sizes, int n_in,
                              void* d_out, int out_size) {
    (void)in_sizes; (void)n_in; (void)out_size;
    const float* x       = (const float*)d_in[0];
    const int*   qweight = (const int*)d_in[1];
    const float* scales  = (const float*)d_in[2];
    const int*   qzeros  = (const int*)d_in[3];
    float* out = (float*)d_out;

    prep_kernel<<<(XWORK + WWORK + 255) / 256, 256>>>(x, qweight, scales, qzeros);

    cudaFuncSetAttribute(gemm_kernel, cudaFuncAttributeMaxDynamicSharedMemorySize,
                         SMEM_BYTES);
    dim3 grid(M / BM, N / BN);   // (64, 43), m-fast: wave working set fits L2
    gemm_kernel<<<grid, THREADS, SMEM_BYTES>>>(out);
}